// round 17
// baseline (speedup 1.0000x reference)
#include <cuda_runtime.h>
#include <cuda_fp16.h>
#include <cstdint>

#define BD 2
#define TT 2048
#define CC 2048
#define NH 16
#define HD 128
#define MTOT (BD*TT)
#define BHH (BD*NH)
typedef __half f16;
typedef __half2 f162;

__device__ f16 g_xh[MTOT*CC];
__device__ f16 g_wh[4][CC*CC];     // wq (pre-scaled), wk, wv, wo — hi only
__device__ f16 g_qh[BHH*TT*HD];
__device__ f16 g_kh[BHH*TT*HD];
__device__ f16 g_vth[BHH*HD*TT];
__device__ f16 g_yh[MTOT*CC];

// ---- helpers ----
__device__ __forceinline__ uint32_t su32(const void* p){
    uint32_t a; asm("{.reg .u64 t; cvta.to.shared.u64 t,%1; cvt.u32.u64 %0,t;}":"=r"(a):"l"(p)); return a;
}
#define CP_ASYNC16(s,g) asm volatile("cp.async.cg.shared.global [%0], [%1], 16;" ::"r"(s),"l"(g))
#define CP_COMMIT() asm volatile("cp.async.commit_group;" ::: "memory")
#define LDSM4(r0,r1,r2,r3,addr) \
    asm volatile("ldmatrix.sync.aligned.m8n8.x4.shared.b16 {%0,%1,%2,%3},[%4];" \
                 :"=r"(r0),"=r"(r1),"=r"(r2),"=r"(r3):"r"(addr))

__device__ __forceinline__ void mma16816(float* d, const uint32_t* a, const uint32_t* b){
    asm volatile("mma.sync.aligned.m16n8k16.row.col.f32.f16.f16.f32 "
        "{%0,%1,%2,%3},{%4,%5,%6,%7},{%8,%9},{%0,%1,%2,%3};"
        : "+f"(d[0]),"+f"(d[1]),"+f"(d[2]),"+f"(d[3])
        : "r"(a[0]),"r"(a[1]),"r"(a[2]),"r"(a[3]),"r"(b[0]),"r"(b[1]));
}

__device__ __forceinline__ uint32_t pack2(float x, float y){
    f162 t = __halves2half2(__float2half(x), __float2half(y));
    return *(uint32_t*)&t;
}

// ---- conversions (fp32 -> fp16; wq pre-scaled by 1/sqrt(HD)) ----
__global__ __launch_bounds__(256) void split_x(const float* __restrict__ s){
    int i = blockIdx.x*256 + threadIdx.x;
    float4 v = ((const float4*)s)[i];
    ((f162*)g_xh)[2*i  ] = __halves2half2(__float2half(v.x), __float2half(v.y));
    ((f162*)g_xh)[2*i+1] = __halves2half2(__float2half(v.z), __float2half(v.w));
}
__global__ __launch_bounds__(256) void split_w(const float* __restrict__ w0,
                                               const float* __restrict__ w1,
                                               const float* __restrict__ w2,
                                               const float* __restrict__ w3){
    int wi = blockIdx.y;
    const float* s = (wi==0)?w0:(wi==1)?w1:(wi==2)?w2:w3;
    float sc = (wi==0) ? 0.08838834764831845f : 1.0f;
    int i = blockIdx.x*256 + threadIdx.x;
    float4 v = ((const float4*)s)[i];
    ((f162*)g_wh[wi])[2*i  ] = __halves2half2(__float2half(v.x*sc), __float2half(v.y*sc));
    ((f162*)g_wh[wi])[2*i+1] = __halves2half2(__float2half(v.z*sc), __float2half(v.w*sc));
}

// ---- warp-MMA GEMM: 128x128 tile, 4 warps (64x64), BK=64, all 1-pass ----
// MODE 0: QKV (z: 0=Q, 1=K, 2=V^T). MODE 1: out-proj.
#define BK 64
#define AS 72
#define TILE_B (128*AS*2)
#define SMEM_DYN (4*TILE_B)

template<int MODE>
__global__ __launch_bounds__(128, 2) void tc_gemm(float* __restrict__ outf)
{
    extern __shared__ f16 smem[];
    uint32_t sb = su32(smem);
    const int tid = threadIdx.x, wid = tid>>5, lane = tid&31;
    const int wm = wid&1, wn = wid>>1;
    const int n0 = blockIdx.x*128, m0 = blockIdx.y*128, z = blockIdx.z;

    const f16 *Ah,*Bh;
    if (MODE==0){ Ah=g_xh; Bh=g_wh[z]; }
    else        { Ah=g_yh; Bh=g_wh[3]; }
    const int K = CC, NC = K/BK;

    auto load_chunk = [&](int c, int b){
        int kk = c*BK;
        uint32_t sa = sb + b*TILE_B;
        uint32_t sB = sb + 2*TILE_B + b*TILE_B;
#pragma unroll
        for (int j=0;j<8;j++){
            int lin = j*128+tid, row = lin>>3, c16 = lin&7;
            CP_ASYNC16(sa + row*(AS*2) + c16*16, Ah + (size_t)(m0+row)*K + kk + c16*8);
        }
#pragma unroll
        for (int j=0;j<8;j++){
            int lin = j*128+tid, row = lin>>3, c16 = lin&7;
            CP_ASYNC16(sB + row*(AS*2) + c16*16, Bh + (size_t)(n0+row)*K + kk + c16*8);
        }
        CP_COMMIT();
    };

    float acc[4][8][4];
#pragma unroll
    for (int mi=0;mi<4;mi++)
#pragma unroll
        for (int ni=0;ni<8;ni++)
#pragma unroll
            for (int r=0;r<4;r++) acc[mi][ni][r] = 0.0f;

    load_chunk(0,0);
    for (int c=0;c<NC;c++){
        if (c+1<NC){ load_chunk(c+1,(c+1)&1); asm volatile("cp.async.wait_group 1;":::"memory"); }
        else asm volatile("cp.async.wait_group 0;":::"memory");
        __syncthreads();
        uint32_t sa = sb + (c&1)*TILE_B;
        uint32_t sB = sb + 2*TILE_B + (c&1)*TILE_B;
#pragma unroll
        for (int ks=0;ks<BK;ks+=16){
            uint32_t af[4][4], bfr[8][2];
#pragma unroll
            for (int mi=0;mi<4;mi++){
                int r = wm*64 + mi*16 + (lane&15);
                uint32_t addr = sa + r*(AS*2) + (ks + ((lane>>4)<<3))*2;
                LDSM4(af[mi][0],af[mi][1],af[mi][2],af[mi][3], addr);
            }
#pragma unroll
            for (int g=0;g<4;g++){
                int nr = wn*64 + g*16 + ((lane>>4)<<3) + (lane&7);
                uint32_t addr = sB + nr*(AS*2) + (ks + ((lane>>3)&1)*8)*2;
                uint32_t r0,r1,r2,r3;
                LDSM4(r0,r1,r2,r3, addr);
                bfr[2*g][0]=r0; bfr[2*g][1]=r1; bfr[2*g+1][0]=r2; bfr[2*g+1][1]=r3;
            }
#pragma unroll
            for (int mi=0;mi<4;mi++)
#pragma unroll
                for (int ni=0;ni<8;ni++)
                    mma16816(acc[mi][ni], af[mi], bfr[ni]);
        }
        __syncthreads();
    }

    const int lrow = lane>>2, lcol = (lane&3)*2;
#pragma unroll
    for (int mi=0;mi<4;mi++){
#pragma unroll
        for (int ni=0;ni<8;ni++){
            int cw = wn*64 + ni*8 + lcol;
            int n  = n0 + cw;
#pragma unroll
            for (int half=0; half<2; half++){
                int m = m0 + wm*64 + mi*16 + lrow + half*8;
                float v0 = acc[mi][ni][2*half], v1 = acc[mi][ni][2*half+1];
                if (MODE==0){
                    int b = m>>11, t = m&(TT-1), h = blockIdx.x, d = cw;
                    if (z==2){
                        size_t o = ((size_t)(b*NH+h)*HD + d)*TT + t;
                        g_vth[o] = __float2half(v0);
                        g_vth[o+TT] = __float2half(v1);
                    } else {
                        f16* dst = (z==0) ? g_qh : g_kh;
                        size_t o = ((size_t)(b*NH+h)*TT + t)*HD + d;
                        *(f162*)&dst[o] = __halves2half2(__float2half(v0), __float2half(v1));
                    }
                } else {
                    *(float2*)&outf[(size_t)m*CC + n] = make_float2(v0, v1);
                }
            }
        }
    }
}

// ---- fused flash attention: 64q x 64k tiles, 4 warps ----
// Q frags in registers; K/V double-buffered.
#define SKQ 136
#define SKV 72
#define QTILE (64*SKQ*2)              // 17408
#define KTILE (64*SKQ*2)              // 17408
#define VTILE (128*SKV*2)             // 18432
#define STAGE (KTILE+VTILE)           // 35840
#define FS_SMEM (QTILE + 2*STAGE)     // 89088

__global__ __launch_bounds__(128, 2) void flash_k()
{
    extern __shared__ f16 fsm[];
    uint32_t sb = su32(fsm);
    const int tid = threadIdx.x, wid = tid>>5, lane = tid&31;
    const int bh = blockIdx.y, q0 = blockIdx.x*64;

    const f16* Qg = g_qh + ((size_t)bh*TT + q0)*HD;
    const f16* Kg = g_kh + (size_t)bh*TT*HD;
    const f16* Vg = g_vth + (size_t)bh*HD*TT;

    auto ldQK = [&](uint32_t dst, const f16* src){
#pragma unroll
        for (int j=0;j<8;j++){
            int lin = j*128+tid, row = lin>>4, c = lin&15;
            CP_ASYNC16(dst + row*(SKQ*2) + c*16, src + (size_t)row*HD + c*8);
        }
    };
    auto ldV = [&](uint32_t dst, const f16* src, int coloff){
#pragma unroll
        for (int j=0;j<8;j++){
            int lin = j*128+tid, row = lin>>3, c = lin&7;
            CP_ASYNC16(dst + row*(SKV*2) + c*16, src + (size_t)row*TT + coloff + c*8);
        }
    };
    auto ldKV = [&](int kt, int s){
        uint32_t base = sb + QTILE + s*STAGE;
        ldQK(base, Kg + (size_t)kt*64*HD);
        ldV(base + KTILE, Vg, kt*64);
        CP_COMMIT();
    };

    // prologue: Q tile + KV tile 0
    ldQK(sb, Qg);
    CP_COMMIT();
    ldKV(0, 0);
    asm volatile("cp.async.wait_group 0;":::"memory");
    __syncthreads();

    // hoist Q fragments to registers (loop-invariant)
    uint32_t qf[8][4];
    {
        int ar = wid*16 + (lane&15);
#pragma unroll
        for (int ks=0;ks<8;ks++){
            uint32_t acol = (ks*16 + ((lane>>4)<<3))*2;
            LDSM4(qf[ks][0],qf[ks][1],qf[ks][2],qf[ks][3], sb + ar*(SKQ*2) + acol);
        }
    }

    float acc[16][4];
#pragma unroll
    for (int j=0;j<16;j++){ acc[j][0]=0;acc[j][1]=0;acc[j][2]=0;acc[j][3]=0; }
    float m0=-1e30f, m1=-1e30f, l0=0.0f, l1=0.0f;

    const int NT = TT/64;
    for (int kt=0; kt<NT; kt++){
        if (kt+1<NT){ ldKV(kt+1, (kt+1)&1); asm volatile("cp.async.wait_group 1;":::"memory"); }
        else        { asm volatile("cp.async.wait_group 0;":::"memory"); }
        __syncthreads();
        uint32_t KB = sb + QTILE + (kt&1)*STAGE;
        uint32_t VB = KB + KTILE;

        // ---- S = QK^T (Q from regs) ----
        float S[8][4];
#pragma unroll
        for (int j=0;j<8;j++){ S[j][0]=0;S[j][1]=0;S[j][2]=0;S[j][3]=0; }
#pragma unroll
        for (int ks=0;ks<8;ks++){
#pragma unroll
            for (int g=0;g<4;g++){
                int nr = g*16 + ((lane>>4)<<3) + (lane&7);
                uint32_t bcol = (ks*16 + ((lane>>3)&1)*8)*2;
                uint32_t h0,h1,h2,h3;
                LDSM4(h0,h1,h2,h3, KB + nr*(SKQ*2) + bcol);
                uint32_t bh0[2]={h0,h1}, bh1[2]={h2,h3};
                mma16816(S[2*g],   qf[ks], bh0); mma16816(S[2*g+1], qf[ks], bh1);
            }
        }

        // ---- online softmax ----
        float mx0=-1e30f, mx1=-1e30f;
#pragma unroll
        for (int j=0;j<8;j++){
            mx0 = fmaxf(mx0, fmaxf(S[j][0],S[j][1]));
            mx1 = fmaxf(mx1, fmaxf(S[j][2],S[j][3]));
        }
        mx0 = fmaxf(mx0, __shfl_xor_sync(~0u,mx0,1)); mx0 = fmaxf(mx0, __shfl_xor_sync(~0u,mx0,2));
        mx1 = fmaxf(mx1, __shfl_xor_sync(~0u,mx1,1)); mx1 = fmaxf(mx1, __shfl_xor_sync(~0u,mx1,2));
        float mn0 = fmaxf(m0,mx0), mn1 = fmaxf(m1,mx1);
        float c0 = __expf(m0-mn0), c1 = __expf(m1-mn1);
        float ls0=0.0f, ls1=0.0f;
#pragma unroll
        for (int j=0;j<8;j++){
            S[j][0]=__expf(S[j][0]-mn0); S[j][1]=__expf(S[j][1]-mn0); ls0 += S[j][0]+S[j][1];
            S[j][2]=__expf(S[j][2]-mn1); S[j][3]=__expf(S[j][3]-mn1); ls1 += S[j][2]+S[j][3];
        }
        ls0 += __shfl_xor_sync(~0u,ls0,1); ls0 += __shfl_xor_sync(~0u,ls0,2);
        ls1 += __shfl_xor_sync(~0u,ls1,1); ls1 += __shfl_xor_sync(~0u,ls1,2);
        l0 = l0*c0 + ls0; l1 = l1*c1 + ls1; m0 = mn0; m1 = mn1;
#pragma unroll
        for (int j=0;j<16;j++){ acc[j][0]*=c0; acc[j][1]*=c0; acc[j][2]*=c1; acc[j][3]*=c1; }

        // ---- acc += P V ----
#pragma unroll
        for (int ks=0;ks<4;ks++){
            uint32_t ph[4];
            ph[0]=pack2(S[2*ks][0],  S[2*ks][1]);   ph[1]=pack2(S[2*ks][2],  S[2*ks][3]);
            ph[2]=pack2(S[2*ks+1][0],S[2*ks+1][1]); ph[3]=pack2(S[2*ks+1][2],S[2*ks+1][3]);
#pragma unroll
            for (int g=0;g<8;g++){
                int nr = g*16 + ((lane>>4)<<3) + (lane&7);
                uint32_t bcol = (ks*16 + ((lane>>3)&1)*8)*2;
                uint32_t h0,h1,h2,h3;
                LDSM4(h0,h1,h2,h3, VB + nr*(SKV*2) + bcol);
                uint32_t bh0[2]={h0,h1}, bh1[2]={h2,h3};
                mma16816(acc[2*g],   ph, bh0); mma16816(acc[2*g+1], ph, bh1);
            }
        }
        __syncthreads();   // all reads of this stage done before it is reloaded
    }

    // ---- write y (fp16) in [B,T,C] ----
    float i0 = 1.0f/l0, i1 = 1.0f/l1;
    int b = bh>>4, h = bh&15;
    int t0 = q0 + wid*16 + (lane>>2);
#pragma unroll
    for (int j=0;j<16;j++){
        int d = j*8 + (lane&3)*2;
        {
            size_t o = ((size_t)(b*TT + t0))*CC + h*HD + d;
            *(f162*)&g_yh[o] = __halves2half2(__float2half(acc[j][0]*i0), __float2half(acc[j][1]*i0));
        }
        {
            size_t o = ((size_t)(b*TT + t0 + 8))*CC + h*HD + d;
            *(f162*)&g_yh[o] = __halves2half2(__float2half(acc[j][2]*i1), __float2half(acc[j][3]*i1));
        }
    }
}

// ---- launch ----
extern "C" void kernel_launch(void* const* d_in, const int* in_sizes, int n_in,
                              void* d_out, int out_size)
{
    const float* x  = (const float*)d_in[0];
    const float* wq = (const float*)d_in[1];
    const float* wk = (const float*)d_in[2];
    const float* wv = (const float*)d_in[3];
    const float* wo = (const float*)d_in[4];
    float* out = (float*)d_out;

    cudaFuncSetAttribute(tc_gemm<0>, cudaFuncAttributeMaxDynamicSharedMemorySize, SMEM_DYN);
    cudaFuncSetAttribute(tc_gemm<1>, cudaFuncAttributeMaxDynamicSharedMemorySize, SMEM_DYN);
    cudaFuncSetAttribute(flash_k,   cudaFuncAttributeMaxDynamicSharedMemorySize, FS_SMEM);

    split_x<<<MTOT*CC/1024, 256>>>(x);
    split_w<<<dim3(CC*CC/1024, 4), 256>>>(wq, wk, wv, wo);

    tc_gemm<0><<<dim3(16,32,3), 128, SMEM_DYN>>>(nullptr);  // Q,K,V^T (1-pass each)
    flash_k<<<dim3(TT/64, BHH), 128, FS_SMEM>>>();           // attention -> y fp16
    tc_gemm<1><<<dim3(16,32), 128, SMEM_DYN>>>(out);         // out-proj
}